// round 1
// baseline (speedup 1.0000x reference)
#include <cuda_runtime.h>
#include <cstdint>

#define NMAX   30000
#define DREP   256
#define KCAPS  8
#define DDIM   32
#define MNBR   16
#define NFEAT  1024
#define NCLS   16

// ---------------- device scratch (static, allocation-free) ----------------
__device__ float g_bufA[NMAX * DREP];
__device__ float g_bufB[NMAX * DREP];
__device__ float g_bufC[NMAX * DREP];

__device__ __forceinline__ float wsum32(float v) {
    v += __shfl_xor_sync(0xffffffffu, v, 16);
    v += __shfl_xor_sync(0xffffffffu, v, 8);
    v += __shfl_xor_sync(0xffffffffu, v, 4);
    v += __shfl_xor_sync(0xffffffffu, v, 2);
    v += __shfl_xor_sync(0xffffffffu, v, 1);
    return v;
}

// ---------------- PCA: out = relu(A[M,1024] @ W[1024,256] + b) ----------------
__global__ void __launch_bounds__(256) pca_kernel(
    const float* __restrict__ A, const float* __restrict__ W,
    const float* __restrict__ bias, float* __restrict__ out, int M)
{
    __shared__ float As[8][128];   // transposed A tile
    __shared__ float Bs[8][128];

    const int tid = threadIdx.x;
    const int bm  = blockIdx.x * 128;
    const int bn  = blockIdx.y * 128;
    const int ty  = tid >> 4;          // 0..15
    const int tx  = tid & 15;          // 0..15
    const int arow  = tid >> 1;        // 0..127
    const int acol4 = (tid & 1) << 2;  // 0 or 4
    const int brow  = tid >> 5;        // 0..7
    const int bcol  = (tid & 31) << 2; // 0..124

    float acc[8][8];
#pragma unroll
    for (int i = 0; i < 8; i++)
#pragma unroll
        for (int j = 0; j < 8; j++) acc[i][j] = 0.f;

    const bool aok = (bm + arow) < M;
    const float* Aptr = A + (size_t)(bm + arow) * NFEAT + acol4;
    const float* Wptr = W + (size_t)brow * DREP + bn + bcol;

    for (int k0 = 0; k0 < NFEAT; k0 += 8) {
        float4 av = aok ? *(const float4*)(Aptr + k0) : make_float4(0.f, 0.f, 0.f, 0.f);
        float4 bv = *(const float4*)(Wptr + (size_t)k0 * DREP);
        As[acol4 + 0][arow] = av.x;
        As[acol4 + 1][arow] = av.y;
        As[acol4 + 2][arow] = av.z;
        As[acol4 + 3][arow] = av.w;
        *(float4*)&Bs[brow][bcol] = bv;
        __syncthreads();
#pragma unroll
        for (int kk = 0; kk < 8; kk++) {
            float ra[8], rb[8];
            *(float4*)(ra)     = *(const float4*)&As[kk][ty * 8];
            *(float4*)(ra + 4) = *(const float4*)&As[kk][ty * 8 + 4];
            *(float4*)(rb)     = *(const float4*)&Bs[kk][tx * 8];
            *(float4*)(rb + 4) = *(const float4*)&Bs[kk][tx * 8 + 4];
#pragma unroll
            for (int i = 0; i < 8; i++)
#pragma unroll
                for (int j = 0; j < 8; j++)
                    acc[i][j] = fmaf(ra[i], rb[j], acc[i][j]);
        }
        __syncthreads();
    }

#pragma unroll
    for (int i = 0; i < 8; i++) {
        int row = bm + ty * 8 + i;
        if (row < M) {
#pragma unroll
            for (int j = 0; j < 8; j++) {
                int col = bn + tx * 8 + j;
                float v = acc[i][j] + bias[col];
                out[(size_t)row * DREP + col] = fmaxf(v, 0.f);
            }
        }
    }
}

// -------- layer-0: per-capsule l2norm -> fc (32x32 per capsule) -> relu -> l2norm --------
__global__ void __launch_bounds__(256) fcnorm_kernel(
    const float* __restrict__ hin, const float* __restrict__ fc_w,
    const float* __restrict__ fc_b, float* __restrict__ znorm, int N)
{
    __shared__ float wt[KCAPS * DDIM * DDIM];  // transposed: [k][i][o]
    __shared__ float bs[KCAPS * DDIM];

    const int tid = threadIdx.x;
    // load fc_w transposed (coalesced read)
    for (int idx = tid; idx < KCAPS * DDIM * DDIM; idx += 256) {
        int k = idx >> 10;
        int o = (idx >> 5) & 31;
        int i = idx & 31;
        wt[k * 1024 + i * 32 + o] = fc_w[idx];
    }
    bs[tid] = fc_b[tid];
    __syncthreads();

    const int k = tid >> 5, lane = tid & 31;
    int node0 = blockIdx.x * 8;
    for (int nn = 0; nn < 8; nn++) {
        int node = node0 + nn;
        if (node >= N) break;
        float v = hin[(size_t)node * DREP + tid];
        float s = wsum32(v * v);
        float xn = v / fmaxf(sqrtf(s), 1e-12f);
        float y = bs[tid];
        const float* wk = &wt[k * 1024];
#pragma unroll
        for (int i = 0; i < 32; i++) {
            float xi = __shfl_sync(0xffffffffu, xn, i);
            y = fmaf(xi, wk[i * 32 + lane], y);
        }
        y = fmaxf(y, 0.f);
        float s2 = wsum32(y * y);
        znorm[(size_t)node * DREP + tid] = y / fmaxf(sqrtf(s2), 1e-12f);
    }
}

// ---------------- routing: one CTA per node, 6 iters in smem ----------------
// out_mode 0: write l2norm(relu(u))  (feeds next routing layer)
// out_mode 1: write u raw            (final embedding)
__global__ void __launch_bounds__(256) route_kernel(
    const float* __restrict__ znorm, const int* __restrict__ nbrs,
    const float* __restrict__ raw_param, const int* __restrict__ routit_p,
    float* __restrict__ outbuf, int out_mode, int N)
{
    // padded layout: z_s[m*264 + k*33 + d]
    __shared__ float z_s[MNBR * 264];
    __shared__ float u_s[264];
    __shared__ float p_s[128];
    __shared__ float wc_s[128];
    __shared__ float cmax_s[KCAPS], crs_s[KCAPS];

    const int node = blockIdx.x;
    const int tid  = threadIdx.x;
    const int k    = tid >> 5, lane = tid & 31;

    const float param = 1.f / (1.f + __expf(-raw_param[0]));
    const float q = 1.f - param;
    const int rt = routit_p ? *routit_p : 6;

    // gather 16 neighbor rows (coalesced reads, padded smem writes)
    const int nbase = node * MNBR;
#pragma unroll
    for (int m = 0; m < MNBR; m++) {
        int nb = nbrs[nbase + m];
        float v = (nb >= 0 && nb < N) ? znorm[(size_t)nb * DREP + tid] : 0.f;
        z_s[m * 264 + k * 33 + lane] = v;
    }
    float ub = znorm[(size_t)node * DREP + tid];
    __syncthreads();

    // iteration 0: p == 0 -> p1 = 1/M, p2 = 1/K
    {
        const float w0 = param * (1.f / 16.f) + q * (1.f / 8.f);
        float a = ub;
#pragma unroll
        for (int m = 0; m < MNBR; m++)
            a = fmaf(z_s[m * 264 + k * 33 + lane], w0, a);
        ub = a;
    }

    for (int it = 1; it < rt; it++) {
        // l2norm of previous u (end-of-prev-iter norm), publish to smem
        float s = wsum32(ub * ub);
        float un = ub / fmaxf(sqrtf(s), 1e-12f);
        u_s[k * 33 + lane] = un;
        __syncthreads();

        float pval = 0.f, p2w = 0.f;
        int kk = 0;
        if (tid < 128) {
            int mm = tid >> 3;
            kk = tid & 7;
            const float* zr = &z_s[mm * 264 + kk * 33];
            const float* ur = &u_s[kk * 33];
            float p = 0.f;
#pragma unroll
            for (int j = 0; j < 32; j++) p = fmaf(zr[j], ur[j], p);
            pval = p;
            // softmax over capsules k (aligned groups of 8 lanes)
            float mx = p;
            mx = fmaxf(mx, __shfl_xor_sync(0xffffffffu, mx, 1));
            mx = fmaxf(mx, __shfl_xor_sync(0xffffffffu, mx, 2));
            mx = fmaxf(mx, __shfl_xor_sync(0xffffffffu, mx, 4));
            float e = __expf(p - mx);
            float es = e;
            es += __shfl_xor_sync(0xffffffffu, es, 1);
            es += __shfl_xor_sync(0xffffffffu, es, 2);
            es += __shfl_xor_sync(0xffffffffu, es, 4);
            p2w = e / es;
            p_s[tid] = p;
        }
        __syncthreads();
        // column stats for softmax over neighbors m (per capsule k)
        if (tid < KCAPS) {
            float mx = -3.4e38f;
#pragma unroll
            for (int m = 0; m < MNBR; m++) mx = fmaxf(mx, p_s[m * 8 + tid]);
            float ssum = 0.f;
#pragma unroll
            for (int m = 0; m < MNBR; m++) ssum += __expf(p_s[m * 8 + tid] - mx);
            cmax_s[tid] = mx;
            crs_s[tid]  = 1.f / ssum;
        }
        __syncthreads();
        if (tid < 128) {
            float p1w = __expf(pval - cmax_s[kk]) * crs_s[kk];
            wc_s[tid] = param * p1w + q * p2w;
        }
        __syncthreads();
        // u update: u = u_before + sum_m z[m] * wc[m]
        float a = ub;
#pragma unroll
        for (int m = 0; m < MNBR; m++)
            a = fmaf(z_s[m * 264 + k * 33 + lane], wc_s[m * 8 + k], a);
        ub = a;
    }

    if (out_mode == 0) {
        float r = fmaxf(ub, 0.f);
        float s = wsum32(r * r);
        outbuf[(size_t)node * DREP + tid] = r / fmaxf(sqrtf(s), 1e-12f);
    } else {
        outbuf[(size_t)node * DREP + tid] = ub;
    }
}

// ---------------- classifier: logit = h @ mlp_w^T + b; log_softmax; copy h ----------------
__global__ void __launch_bounds__(256) cls_kernel(
    const float* __restrict__ h, const float* __restrict__ mw,
    const float* __restrict__ mb, float* __restrict__ outLogp,
    float* __restrict__ outH, int N)
{
    __shared__ float lgs[8][17];
    const int w = threadIdx.x >> 5, lane = threadIdx.x & 31;
    const int node = blockIdx.x * 8 + w;
    if (node >= N) return;

    float hreg[8];
#pragma unroll
    for (int j = 0; j < 8; j++) hreg[j] = h[(size_t)node * DREP + j * 32 + lane];
    if (outH) {
#pragma unroll
        for (int j = 0; j < 8; j++) outH[(size_t)node * DREP + j * 32 + lane] = hreg[j];
    }

    float logit[NCLS];
#pragma unroll
    for (int c = 0; c < NCLS; c++) {
        float a = 0.f;
#pragma unroll
        for (int j = 0; j < 8; j++)
            a = fmaf(hreg[j], mw[c * DREP + j * 32 + lane], a);
        a += __shfl_xor_sync(0xffffffffu, a, 16);
        a += __shfl_xor_sync(0xffffffffu, a, 8);
        a += __shfl_xor_sync(0xffffffffu, a, 4);
        a += __shfl_xor_sync(0xffffffffu, a, 2);
        a += __shfl_xor_sync(0xffffffffu, a, 1);
        logit[c] = a + mb[c];
    }
    float mx = logit[0];
#pragma unroll
    for (int c = 1; c < NCLS; c++) mx = fmaxf(mx, logit[c]);
    float ssum = 0.f;
#pragma unroll
    for (int c = 0; c < NCLS; c++) ssum += expf(logit[c] - mx);
    float L = mx + logf(ssum);
    if (lane == 0) {
#pragma unroll
        for (int c = 0; c < NCLS; c++) lgs[w][c] = logit[c];
    }
    __syncwarp();
    if (lane < NCLS)
        outLogp[(size_t)node * NCLS + lane] = lgs[w][lane] - L;
}

__global__ void copy_kernel(const float* __restrict__ src, float* __restrict__ dst, int n)
{
    int i = blockIdx.x * blockDim.x + threadIdx.x;
    if (i < n) dst[i] = src[i];
}

// ---------------- launch ----------------
extern "C" void kernel_launch(void* const* d_in, const int* in_sizes, int n_in,
                              void* d_out, int out_size)
{
    const float* x         = (const float*)d_in[0];
    const int*   nbrs      = (const int*)  d_in[1];
    const float* pca_w     = (const float*)d_in[2];
    const float* pca_b     = (const float*)d_in[3];
    const float* raw_param = (const float*)d_in[4];
    const float* fc_w      = (const float*)d_in[5];
    const float* fc_b      = (const float*)d_in[6];
    const float* mlp_w     = (const float*)d_in[7];
    const float* mlp_b     = (const float*)d_in[8];
    const int*   routit    = (n_in > 9) ? (const int*)d_in[9] : nullptr;

    const int N = in_sizes[0] / NFEAT;

    float *bufA, *bufB, *bufC;
    cudaGetSymbolAddress((void**)&bufA, g_bufA);
    cudaGetSymbolAddress((void**)&bufB, g_bufB);
    cudaGetSymbolAddress((void**)&bufC, g_bufC);

    // 1) h0 = relu(x @ pca_w + pca_b)
    dim3 pgrid((N + 127) / 128, DREP / 128);
    pca_kernel<<<pgrid, 256>>>(x, pca_w, pca_b, bufA, N);

    // 2) layer-0 front end: l2norm -> per-capsule fc -> relu -> l2norm
    fcnorm_kernel<<<(N + 7) / 8, 256>>>(bufA, fc_w, fc_b, bufB, N);

    // 3) three routing layers (intermediate relu+l2norm fused in epilogue)
    route_kernel<<<N, 256>>>(bufB, nbrs, raw_param, routit, bufA, 0, N);
    route_kernel<<<N, 256>>>(bufA, nbrs, raw_param, routit, bufB, 0, N);
    route_kernel<<<N, 256>>>(bufB, nbrs, raw_param, routit, bufC, 1, N);

    // 4) classifier + output assembly (adaptive to harness output layout)
    float* out = (float*)d_out;
    if (out_size == N * (NCLS + DREP)) {
        cls_kernel<<<(N + 7) / 8, 256>>>(bufC, mlp_w, mlp_b, out, out + (size_t)N * NCLS, N);
    } else if (out_size == N * NCLS) {
        cls_kernel<<<(N + 7) / 8, 256>>>(bufC, mlp_w, mlp_b, out, nullptr, N);
    } else {
        // assume embedding-only output
        int n = N * DREP;
        copy_kernel<<<(n + 255) / 256, 256>>>(bufC, out, n);
    }
}

// round 3
// speedup vs baseline: 1.2050x; 1.2050x over previous
#include <cuda_runtime.h>
#include <cstdint>

#define NMAX   30000
#define DREP   256
#define KCAPS  8
#define DDIM   32
#define MNBR   16
#define NFEAT  1024
#define NCLS   16
#define ZSTR   36   // padded row stride (floats) for z_s / u_s: 16B-aligned, conflict-free

// ---------------- device scratch (static, allocation-free) ----------------
__device__ float g_bufA[NMAX * DREP];
__device__ float g_bufB[NMAX * DREP];
__device__ float g_bufC[NMAX * DREP];

__device__ __forceinline__ float wsum32(float v) {
    v += __shfl_xor_sync(0xffffffffu, v, 16);
    v += __shfl_xor_sync(0xffffffffu, v, 8);
    v += __shfl_xor_sync(0xffffffffu, v, 4);
    v += __shfl_xor_sync(0xffffffffu, v, 2);
    v += __shfl_xor_sync(0xffffffffu, v, 1);
    return v;
}

// packed f32x2 helpers (Blackwell sm_103a)
__device__ __forceinline__ unsigned long long dup2(float x) {
    unsigned long long r;
    asm("mov.b64 %0, {%1, %1};" : "=l"(r) : "f"(x));
    return r;
}
__device__ __forceinline__ void ffma2(unsigned long long& d,
                                      unsigned long long a, unsigned long long b) {
    asm("fma.rn.f32x2 %0, %1, %2, %0;" : "+l"(d) : "l"(a), "l"(b));
}
__device__ __forceinline__ void unpack2(unsigned long long v, float& lo, float& hi) {
    asm("mov.b64 {%0, %1}, %2;" : "=f"(lo), "=f"(hi) : "l"(v));
}

// ---------------- PCA: out = relu(A[M,1024] @ W[1024,256] + b) ----------------
// 128x128 tile, K-step 16, packed f32x2 FMA inner loop.
__global__ void __launch_bounds__(256) pca_kernel(
    const float* __restrict__ A, const float* __restrict__ W,
    const float* __restrict__ bias, float* __restrict__ out, int M)
{
    __shared__ __align__(16) float As[16][128];   // transposed A tile: As[k][row]
    __shared__ __align__(16) float Bs[16][128];   // Bs[k][col]

    const int tid = threadIdx.x;
    const int bm  = blockIdx.x * 128;
    const int bn  = blockIdx.y * 128;
    const int ty  = tid >> 4;          // 0..15 (row group)
    const int tx  = tid & 15;          // 0..15 (col group)

    // A load mapping: thread covers A[bm+arow][k0+kb .. k0+kb+7] (2 x float4)
    const int arow = tid & 127;
    const int kb   = (tid >> 7) * 8;   // 0 or 8
    // B load mapping: thread covers W[k0+brow][bn+bcol..+3] and W[k0+brow+8][...]
    const int brow = tid >> 5;         // 0..7
    const int bcol = (tid & 31) * 4;   // 0..124

    unsigned long long acc[8][4];
#pragma unroll
    for (int i = 0; i < 8; i++)
#pragma unroll
        for (int j = 0; j < 4; j++) acc[i][j] = 0ull;

    const bool aok = (bm + arow) < M;
    const float* Aptr = A + (size_t)(bm + arow) * NFEAT + kb;
    const float* Wptr = W + (size_t)brow * DREP + bn + bcol;

    for (int k0 = 0; k0 < NFEAT; k0 += 16) {
        float4 a0 = make_float4(0.f, 0.f, 0.f, 0.f), a1 = a0;
        if (aok) {
            a0 = *(const float4*)(Aptr + k0);
            a1 = *(const float4*)(Aptr + k0 + 4);
        }
        float4 b0 = *(const float4*)(Wptr + (size_t)k0 * DREP);
        float4 b1 = *(const float4*)(Wptr + (size_t)(k0 + 8) * DREP);
        __syncthreads();
        As[kb + 0][arow] = a0.x; As[kb + 1][arow] = a0.y;
        As[kb + 2][arow] = a0.z; As[kb + 3][arow] = a0.w;
        As[kb + 4][arow] = a1.x; As[kb + 5][arow] = a1.y;
        As[kb + 6][arow] = a1.z; As[kb + 7][arow] = a1.w;
        *(float4*)&Bs[brow][bcol]     = b0;
        *(float4*)&Bs[brow + 8][bcol] = b1;
        __syncthreads();
#pragma unroll
        for (int kk = 0; kk < 16; kk++) {
            float ra[8];
            *(float4*)(ra)     = *(const float4*)&As[kk][ty * 8];
            *(float4*)(ra + 4) = *(const float4*)&As[kk][ty * 8 + 4];
            unsigned long long rb[4];
            rb[0] = *(const unsigned long long*)&Bs[kk][tx * 8];
            rb[1] = *(const unsigned long long*)&Bs[kk][tx * 8 + 2];
            rb[2] = *(const unsigned long long*)&Bs[kk][tx * 8 + 4];
            rb[3] = *(const unsigned long long*)&Bs[kk][tx * 8 + 6];
#pragma unroll
            for (int i = 0; i < 8; i++) {
                unsigned long long a2 = dup2(ra[i]);
#pragma unroll
                for (int j = 0; j < 4; j++) ffma2(acc[i][j], a2, rb[j]);
            }
        }
    }

#pragma unroll
    for (int i = 0; i < 8; i++) {
        int row = bm + ty * 8 + i;
        if (row < M) {
#pragma unroll
            for (int j = 0; j < 4; j++) {
                float lo, hi;
                unpack2(acc[i][j], lo, hi);
                int col = bn + tx * 8 + j * 2;
                out[(size_t)row * DREP + col]     = fmaxf(lo + bias[col], 0.f);
                out[(size_t)row * DREP + col + 1] = fmaxf(hi + bias[col + 1], 0.f);
            }
        }
    }
}

// -------- layer-0: per-capsule l2norm -> fc (32x32 per capsule) -> relu -> l2norm --------
__global__ void __launch_bounds__(256) fcnorm_kernel(
    const float* __restrict__ hin, const float* __restrict__ fc_w,
    const float* __restrict__ fc_b, float* __restrict__ znorm, int N)
{
    __shared__ float wt[KCAPS * DDIM * DDIM];  // transposed: [k][i][o]
    __shared__ float bs[KCAPS * DDIM];

    const int tid = threadIdx.x;
    for (int idx = tid; idx < KCAPS * DDIM * DDIM; idx += 256) {
        int k = idx >> 10;
        int o = (idx >> 5) & 31;
        int i = idx & 31;
        wt[k * 1024 + i * 32 + o] = fc_w[idx];
    }
    bs[tid] = fc_b[tid];
    __syncthreads();

    const int k = tid >> 5, lane = tid & 31;
    int node0 = blockIdx.x * 8;
    for (int nn = 0; nn < 8; nn++) {
        int node = node0 + nn;
        if (node >= N) break;
        float v = hin[(size_t)node * DREP + tid];
        float s = wsum32(v * v);
        float xn = v / fmaxf(sqrtf(s), 1e-12f);
        float y = bs[tid];
        const float* wk = &wt[k * 1024];
#pragma unroll
        for (int i = 0; i < 32; i++) {
            float xi = __shfl_sync(0xffffffffu, xn, i);
            y = fmaf(xi, wk[i * 32 + lane], y);
        }
        y = fmaxf(y, 0.f);
        float s2 = wsum32(y * y);
        znorm[(size_t)node * DREP + tid] = y / fmaxf(sqrtf(s2), 1e-12f);
    }
}

// ---------------- routing v2: one CTA per node, z in registers, 6 iters ----------------
// out_mode 0: write l2norm(relu(u))  (feeds next routing layer)
// out_mode 1: write u raw            (final embedding)
__global__ void __launch_bounds__(256) route_kernel(
    const float* __restrict__ znorm, const int* __restrict__ nbrs,
    const float* __restrict__ raw_param, const int* __restrict__ routit_p,
    float* __restrict__ outbuf, int out_mode, int N)
{
    // z_s layout: [(k*16+m)*ZSTR + d]  (rows 16B-aligned, conflict-free LDS.128)
    __shared__ __align__(16) float z_s[KCAPS * MNBR * ZSTR];
    __shared__ __align__(16) float u_s[KCAPS * ZSTR];
    __shared__ __align__(16) float p_s[KCAPS * MNBR];    // [kk*16+mm]
    __shared__ __align__(16) float wc_s[KCAPS * MNBR];   // [kk*16+mm]

    const int node = blockIdx.x;
    const int tid  = threadIdx.x;
    const int k    = tid >> 5, lane = tid & 31;

    const float param = 1.f / (1.f + __expf(-raw_param[0]));
    const float q = 1.f - param;
    const int rt = routit_p ? *routit_p : 6;

    // gather 16 neighbor rows: registers + smem copy
    float zreg[MNBR];
    const int nbase = node * MNBR;
#pragma unroll
    for (int m = 0; m < MNBR; m++) {
        int nb = nbrs[nbase + m];
        float v = (nb >= 0 && nb < N) ? znorm[(size_t)nb * DREP + tid] : 0.f;
        zreg[m] = v;
        z_s[(k * MNBR + m) * ZSTR + lane] = v;
    }
    float ub = znorm[(size_t)node * DREP + tid];

    // iteration 0: p == 0 -> p1 = 1/M, p2 = 1/K  (pure registers)
    {
        const float w0 = param * (1.f / 16.f) + q * (1.f / 8.f);
        float a = ub;
#pragma unroll
        for (int m = 0; m < MNBR; m++) a = fmaf(zreg[m], w0, a);
        ub = a;
    }
    __syncthreads();   // z_s visible before first p-phase

    for (int it = 1; it < rt; it++) {
        // normalize u, publish
        float s = wsum32(ub * ub);
        float un = ub / fmaxf(sqrtf(s), 1e-12f);
        u_s[k * ZSTR + lane] = un;
        __syncthreads();                       // S1

        float p = 0.f;
        if (tid < 128) {
            const int kk = tid >> 4, mm = tid & 15;
            const float4* zr = (const float4*)&z_s[(kk * MNBR + mm) * ZSTR];
            const float4* ur = (const float4*)&u_s[kk * ZSTR];
#pragma unroll
            for (int j = 0; j < 8; j++) {
                float4 zv = zr[j], uv = ur[j];
                p = fmaf(zv.x, uv.x, p);
                p = fmaf(zv.y, uv.y, p);
                p = fmaf(zv.z, uv.z, p);
                p = fmaf(zv.w, uv.w, p);
            }
            p_s[tid] = p;
        }
        __syncthreads();                       // S2

        if (tid < 128) {
            const int mm = tid & 15;
            // softmax over neighbors m (p1): 16-lane shfl group
            float mx = p;
            mx = fmaxf(mx, __shfl_xor_sync(0xffffffffu, mx, 1));
            mx = fmaxf(mx, __shfl_xor_sync(0xffffffffu, mx, 2));
            mx = fmaxf(mx, __shfl_xor_sync(0xffffffffu, mx, 4));
            mx = fmaxf(mx, __shfl_xor_sync(0xffffffffu, mx, 8));
            float e1 = __expf(p - mx);
            float es = e1;
            es += __shfl_xor_sync(0xffffffffu, es, 1);
            es += __shfl_xor_sync(0xffffffffu, es, 2);
            es += __shfl_xor_sync(0xffffffffu, es, 4);
            es += __shfl_xor_sync(0xffffffffu, es, 8);
            float p1w = e1 / es;
            // softmax over capsules k (p2): multicast smem reads
            float mx2 = -3.4e38f;
#pragma unroll
            for (int j = 0; j < KCAPS; j++) mx2 = fmaxf(mx2, p_s[j * MNBR + mm]);
            float es2 = 0.f;
#pragma unroll
            for (int j = 0; j < KCAPS; j++) es2 += __expf(p_s[j * MNBR + mm] - mx2);
            float p2w = __expf(p - mx2) / es2;
            wc_s[tid] = param * p1w + q * p2w;
        }
        __syncthreads();                       // S3

        // u update: pure register FMA, wc via float4 broadcast
        float w[MNBR];
        const float4* wr = (const float4*)&wc_s[k * MNBR];
#pragma unroll
        for (int j = 0; j < 4; j++) {
            float4 wv = wr[j];
            w[j * 4 + 0] = wv.x; w[j * 4 + 1] = wv.y;
            w[j * 4 + 2] = wv.z; w[j * 4 + 3] = wv.w;
        }
        float a = ub;
#pragma unroll
        for (int m = 0; m < MNBR; m++) a = fmaf(zreg[m], w[m], a);
        ub = a;
    }

    if (out_mode == 0) {
        float r = fmaxf(ub, 0.f);
        float s = wsum32(r * r);
        outbuf[(size_t)node * DREP + tid] = r / fmaxf(sqrtf(s), 1e-12f);
    } else {
        outbuf[(size_t)node * DREP + tid] = ub;
    }
}

// ---------------- classifier: logit = h @ mlp_w^T + b; log_softmax; copy h ----------------
__global__ void __launch_bounds__(256) cls_kernel(
    const float* __restrict__ h, const float* __restrict__ mw,
    const float* __restrict__ mb, float* __restrict__ outLogp,
    float* __restrict__ outH, int N)
{
    __shared__ float lgs[8][17];
    const int w = threadIdx.x >> 5, lane = threadIdx.x & 31;
    const int node = blockIdx.x * 8 + w;
    if (node >= N) return;

    float hreg[8];
#pragma unroll
    for (int j = 0; j < 8; j++) hreg[j] = h[(size_t)node * DREP + j * 32 + lane];
    if (outH) {
#pragma unroll
        for (int j = 0; j < 8; j++) outH[(size_t)node * DREP + j * 32 + lane] = hreg[j];
    }

    float logit[NCLS];
#pragma unroll
    for (int c = 0; c < NCLS; c++) {
        float a = 0.f;
#pragma unroll
        for (int j = 0; j < 8; j++)
            a = fmaf(hreg[j], mw[c * DREP + j * 32 + lane], a);
        a += __shfl_xor_sync(0xffffffffu, a, 16);
        a += __shfl_xor_sync(0xffffffffu, a, 8);
        a += __shfl_xor_sync(0xffffffffu, a, 4);
        a += __shfl_xor_sync(0xffffffffu, a, 2);
        a += __shfl_xor_sync(0xffffffffu, a, 1);
        logit[c] = a + mb[c];
    }
    float mx = logit[0];
#pragma unroll
    for (int c = 1; c < NCLS; c++) mx = fmaxf(mx, logit[c]);
    float ssum = 0.f;
#pragma unroll
    for (int c = 0; c < NCLS; c++) ssum += expf(logit[c] - mx);
    float L = mx + logf(ssum);
    if (lane == 0) {
#pragma unroll
        for (int c = 0; c < NCLS; c++) lgs[w][c] = logit[c];
    }
    __syncwarp();
    if (lane < NCLS)
        outLogp[(size_t)node * NCLS + lane] = lgs[w][lane] - L;
}

__global__ void copy_kernel(const float* __restrict__ src, float* __restrict__ dst, int n)
{
    int i = blockIdx.x * blockDim.x + threadIdx.x;
    if (i < n) dst[i] = src[i];
}

// ---------------- launch ----------------
extern "C" void kernel_launch(void* const* d_in, const int* in_sizes, int n_in,
                              void* d_out, int out_size)
{
    const float* x         = (const float*)d_in[0];
    const int*   nbrs      = (const int*)  d_in[1];
    const float* pca_w     = (const float*)d_in[2];
    const float* pca_b     = (const float*)d_in[3];
    const float* raw_param = (const float*)d_in[4];
    const float* fc_w      = (const float*)d_in[5];
    const float* fc_b      = (const float*)d_in[6];
    const float* mlp_w     = (const float*)d_in[7];
    const float* mlp_b     = (const float*)d_in[8];
    const int*   routit    = (n_in > 9) ? (const int*)d_in[9] : nullptr;

    const int N = in_sizes[0] / NFEAT;

    float *bufA, *bufB, *bufC;
    cudaGetSymbolAddress((void**)&bufA, g_bufA);
    cudaGetSymbolAddress((void**)&bufB, g_bufB);
    cudaGetSymbolAddress((void**)&bufC, g_bufC);

    // 1) h0 = relu(x @ pca_w + pca_b)
    dim3 pgrid((N + 127) / 128, DREP / 128);
    pca_kernel<<<pgrid, 256>>>(x, pca_w, pca_b, bufA, N);

    // 2) layer-0 front end: l2norm -> per-capsule fc -> relu -> l2norm
    fcnorm_kernel<<<(N + 7) / 8, 256>>>(bufA, fc_w, fc_b, bufB, N);

    // 3) three routing layers (intermediate relu+l2norm fused in epilogue)
    route_kernel<<<N, 256>>>(bufB, nbrs, raw_param, routit, bufA, 0, N);
    route_kernel<<<N, 256>>>(bufA, nbrs, raw_param, routit, bufB, 0, N);
    route_kernel<<<N, 256>>>(bufB, nbrs, raw_param, routit, bufC, 1, N);

    // 4) classifier + output assembly (adaptive to harness output layout)
    float* out = (float*)d_out;
    if (out_size == N * (NCLS + DREP)) {
        cls_kernel<<<(N + 7) / 8, 256>>>(bufC, mlp_w, mlp_b, out, out + (size_t)N * NCLS, N);
    } else if (out_size == N * NCLS) {
        cls_kernel<<<(N + 7) / 8, 256>>>(bufC, mlp_w, mlp_b, out, nullptr, N);
    } else {
        int n = N * DREP;
        copy_kernel<<<(n + 255) / 256, 256>>>(bufC, out, n);
    }
}

// round 4
// speedup vs baseline: 1.2054x; 1.0003x over previous
#include <cuda_runtime.h>
#include <cstdint>

#define NMAX   30000
#define DREP   256
#define KCAPS  8
#define DDIM   32
#define MNBR   16
#define NFEAT  1024
#define NCLS   16
#define ZSTR   36   // padded row stride (floats) for z_s / u_s: 16B-aligned, conflict-free

// ---------------- device scratch (static, allocation-free) ----------------
__device__ float g_bufA[NMAX * DREP];
__device__ float g_bufB[NMAX * DREP];
__device__ float g_bufC[NMAX * DREP];

__device__ __forceinline__ float wsum32(float v) {
    v += __shfl_xor_sync(0xffffffffu, v, 16);
    v += __shfl_xor_sync(0xffffffffu, v, 8);
    v += __shfl_xor_sync(0xffffffffu, v, 4);
    v += __shfl_xor_sync(0xffffffffu, v, 2);
    v += __shfl_xor_sync(0xffffffffu, v, 1);
    return v;
}

// packed f32x2 helpers (Blackwell sm_103a)
__device__ __forceinline__ unsigned long long dup2(float x) {
    unsigned long long r;
    asm("mov.b64 %0, {%1, %1};" : "=l"(r) : "f"(x));
    return r;
}
__device__ __forceinline__ void ffma2(unsigned long long& d,
                                      unsigned long long a, unsigned long long b) {
    asm("fma.rn.f32x2 %0, %1, %2, %0;" : "+l"(d) : "l"(a), "l"(b));
}
__device__ __forceinline__ void unpack2(unsigned long long v, float& lo, float& hi) {
    asm("mov.b64 {%0, %1}, %2;" : "=f"(lo), "=f"(hi) : "l"(v));
}

// ---------------- PCA: out = relu(A[M,1024] @ W[1024,256] + b) ----------------
// 128x128 tile, K-step 16, packed f32x2 FMA inner loop.
__global__ void __launch_bounds__(256) pca_kernel(
    const float* __restrict__ A, const float* __restrict__ W,
    const float* __restrict__ bias, float* __restrict__ out, int M)
{
    __shared__ __align__(16) float As[16][128];   // transposed A tile: As[k][row]
    __shared__ __align__(16) float Bs[16][128];   // Bs[k][col]

    const int tid = threadIdx.x;
    const int bm  = blockIdx.x * 128;
    const int bn  = blockIdx.y * 128;
    const int ty  = tid >> 4;          // 0..15 (row group)
    const int tx  = tid & 15;          // 0..15 (col group)

    // A load mapping: thread covers A[bm+arow][k0+kb .. k0+kb+7] (2 x float4)
    const int arow = tid & 127;
    const int kb   = (tid >> 7) * 8;   // 0 or 8
    // B load mapping: thread covers W[k0+brow][bn+bcol..+3] and W[k0+brow+8][...]
    const int brow = tid >> 5;         // 0..7
    const int bcol = (tid & 31) * 4;   // 0..124

    unsigned long long acc[8][4];
#pragma unroll
    for (int i = 0; i < 8; i++)
#pragma unroll
        for (int j = 0; j < 4; j++) acc[i][j] = 0ull;

    const bool aok = (bm + arow) < M;
    const float* Aptr = A + (size_t)(bm + arow) * NFEAT + kb;
    const float* Wptr = W + (size_t)brow * DREP + bn + bcol;

    for (int k0 = 0; k0 < NFEAT; k0 += 16) {
        float4 a0 = make_float4(0.f, 0.f, 0.f, 0.f), a1 = a0;
        if (aok) {
            a0 = *(const float4*)(Aptr + k0);
            a1 = *(const float4*)(Aptr + k0 + 4);
        }
        float4 b0 = *(const float4*)(Wptr + (size_t)k0 * DREP);
        float4 b1 = *(const float4*)(Wptr + (size_t)(k0 + 8) * DREP);
        __syncthreads();
        As[kb + 0][arow] = a0.x; As[kb + 1][arow] = a0.y;
        As[kb + 2][arow] = a0.z; As[kb + 3][arow] = a0.w;
        As[kb + 4][arow] = a1.x; As[kb + 5][arow] = a1.y;
        As[kb + 6][arow] = a1.z; As[kb + 7][arow] = a1.w;
        *(float4*)&Bs[brow][bcol]     = b0;
        *(float4*)&Bs[brow + 8][bcol] = b1;
        __syncthreads();
#pragma unroll
        for (int kk = 0; kk < 16; kk++) {
            float ra[8];
            *(float4*)(ra)     = *(const float4*)&As[kk][ty * 8];
            *(float4*)(ra + 4) = *(const float4*)&As[kk][ty * 8 + 4];
            unsigned long long rb[4];
            rb[0] = *(const unsigned long long*)&Bs[kk][tx * 8];
            rb[1] = *(const unsigned long long*)&Bs[kk][tx * 8 + 2];
            rb[2] = *(const unsigned long long*)&Bs[kk][tx * 8 + 4];
            rb[3] = *(const unsigned long long*)&Bs[kk][tx * 8 + 6];
#pragma unroll
            for (int i = 0; i < 8; i++) {
                unsigned long long a2 = dup2(ra[i]);
#pragma unroll
                for (int j = 0; j < 4; j++) ffma2(acc[i][j], a2, rb[j]);
            }
        }
    }

#pragma unroll
    for (int i = 0; i < 8; i++) {
        int row = bm + ty * 8 + i;
        if (row < M) {
#pragma unroll
            for (int j = 0; j < 4; j++) {
                float lo, hi;
                unpack2(acc[i][j], lo, hi);
                int col = bn + tx * 8 + j * 2;
                out[(size_t)row * DREP + col]     = fmaxf(lo + bias[col], 0.f);
                out[(size_t)row * DREP + col + 1] = fmaxf(hi + bias[col + 1], 0.f);
            }
        }
    }
}

// -------- layer-0: per-capsule l2norm -> fc (32x32 per capsule) -> relu -> l2norm --------
__global__ void __launch_bounds__(256) fcnorm_kernel(
    const float* __restrict__ hin, const float* __restrict__ fc_w,
    const float* __restrict__ fc_b, float* __restrict__ znorm, int N)
{
    __shared__ float wt[KCAPS * DDIM * DDIM];  // transposed: [k][i][o]
    __shared__ float bs[KCAPS * DDIM];

    const int tid = threadIdx.x;
    for (int idx = tid; idx < KCAPS * DDIM * DDIM; idx += 256) {
        int k = idx >> 10;
        int o = (idx >> 5) & 31;
        int i = idx & 31;
        wt[k * 1024 + i * 32 + o] = fc_w[idx];
    }
    bs[tid] = fc_b[tid];
    __syncthreads();

    const int k = tid >> 5, lane = tid & 31;
    int node0 = blockIdx.x * 8;
    for (int nn = 0; nn < 8; nn++) {
        int node = node0 + nn;
        if (node >= N) break;
        float v = hin[(size_t)node * DREP + tid];
        float s = wsum32(v * v);
        float xn = v / fmaxf(sqrtf(s), 1e-12f);
        float y = bs[tid];
        const float* wk = &wt[k * 1024];
#pragma unroll
        for (int i = 0; i < 32; i++) {
            float xi = __shfl_sync(0xffffffffu, xn, i);
            y = fmaf(xi, wk[i * 32 + lane], y);
        }
        y = fmaxf(y, 0.f);
        float s2 = wsum32(y * y);
        znorm[(size_t)node * DREP + tid] = y / fmaxf(sqrtf(s2), 1e-12f);
    }
}

// ---------------- routing v2: one CTA per node, z in registers, 6 iters ----------------
// out_mode 0: write l2norm(relu(u))  (feeds next routing layer)
// out_mode 1: write u raw            (final embedding)
__global__ void __launch_bounds__(256) route_kernel(
    const float* __restrict__ znorm, const int* __restrict__ nbrs,
    const float* __restrict__ raw_param, const int* __restrict__ routit_p,
    float* __restrict__ outbuf, int out_mode, int N)
{
    // z_s layout: [(k*16+m)*ZSTR + d]  (rows 16B-aligned, conflict-free LDS.128)
    __shared__ __align__(16) float z_s[KCAPS * MNBR * ZSTR];
    __shared__ __align__(16) float u_s[KCAPS * ZSTR];
    __shared__ __align__(16) float p_s[KCAPS * MNBR];    // [kk*16+mm]
    __shared__ __align__(16) float wc_s[KCAPS * MNBR];   // [kk*16+mm]

    const int node = blockIdx.x;
    const int tid  = threadIdx.x;
    const int k    = tid >> 5, lane = tid & 31;

    const float param = 1.f / (1.f + __expf(-raw_param[0]));
    const float q = 1.f - param;
    const int rt = routit_p ? *routit_p : 6;

    // gather 16 neighbor rows: registers + smem copy
    float zreg[MNBR];
    const int nbase = node * MNBR;
#pragma unroll
    for (int m = 0; m < MNBR; m++) {
        int nb = nbrs[nbase + m];
        float v = (nb >= 0 && nb < N) ? znorm[(size_t)nb * DREP + tid] : 0.f;
        zreg[m] = v;
        z_s[(k * MNBR + m) * ZSTR + lane] = v;
    }
    float ub = znorm[(size_t)node * DREP + tid];

    // iteration 0: p == 0 -> p1 = 1/M, p2 = 1/K  (pure registers)
    {
        const float w0 = param * (1.f / 16.f) + q * (1.f / 8.f);
        float a = ub;
#pragma unroll
        for (int m = 0; m < MNBR; m++) a = fmaf(zreg[m], w0, a);
        ub = a;
    }
    __syncthreads();   // z_s visible before first p-phase

    for (int it = 1; it < rt; it++) {
        // normalize u, publish
        float s = wsum32(ub * ub);
        float un = ub / fmaxf(sqrtf(s), 1e-12f);
        u_s[k * ZSTR + lane] = un;
        __syncthreads();                       // S1

        float p = 0.f;
        if (tid < 128) {
            const int kk = tid >> 4, mm = tid & 15;
            const float4* zr = (const float4*)&z_s[(kk * MNBR + mm) * ZSTR];
            const float4* ur = (const float4*)&u_s[kk * ZSTR];
#pragma unroll
            for (int j = 0; j < 8; j++) {
                float4 zv = zr[j], uv = ur[j];
                p = fmaf(zv.x, uv.x, p);
                p = fmaf(zv.y, uv.y, p);
                p = fmaf(zv.z, uv.z, p);
                p = fmaf(zv.w, uv.w, p);
            }
            p_s[tid] = p;
        }
        __syncthreads();                       // S2

        if (tid < 128) {
            const int mm = tid & 15;
            // softmax over neighbors m (p1): 16-lane shfl group
            float mx = p;
            mx = fmaxf(mx, __shfl_xor_sync(0xffffffffu, mx, 1));
            mx = fmaxf(mx, __shfl_xor_sync(0xffffffffu, mx, 2));
            mx = fmaxf(mx, __shfl_xor_sync(0xffffffffu, mx, 4));
            mx = fmaxf(mx, __shfl_xor_sync(0xffffffffu, mx, 8));
            float e1 = __expf(p - mx);
            float es = e1;
            es += __shfl_xor_sync(0xffffffffu, es, 1);
            es += __shfl_xor_sync(0xffffffffu, es, 2);
            es += __shfl_xor_sync(0xffffffffu, es, 4);
            es += __shfl_xor_sync(0xffffffffu, es, 8);
            float p1w = e1 / es;
            // softmax over capsules k (p2): multicast smem reads
            float mx2 = -3.4e38f;
#pragma unroll
            for (int j = 0; j < KCAPS; j++) mx2 = fmaxf(mx2, p_s[j * MNBR + mm]);
            float es2 = 0.f;
#pragma unroll
            for (int j = 0; j < KCAPS; j++) es2 += __expf(p_s[j * MNBR + mm] - mx2);
            float p2w = __expf(p - mx2) / es2;
            wc_s[tid] = param * p1w + q * p2w;
        }
        __syncthreads();                       // S3

        // u update: pure register FMA, wc via float4 broadcast
        float w[MNBR];
        const float4* wr = (const float4*)&wc_s[k * MNBR];
#pragma unroll
        for (int j = 0; j < 4; j++) {
            float4 wv = wr[j];
            w[j * 4 + 0] = wv.x; w[j * 4 + 1] = wv.y;
            w[j * 4 + 2] = wv.z; w[j * 4 + 3] = wv.w;
        }
        float a = ub;
#pragma unroll
        for (int m = 0; m < MNBR; m++) a = fmaf(zreg[m], w[m], a);
        ub = a;
    }

    if (out_mode == 0) {
        float r = fmaxf(ub, 0.f);
        float s = wsum32(r * r);
        outbuf[(size_t)node * DREP + tid] = r / fmaxf(sqrtf(s), 1e-12f);
    } else {
        outbuf[(size_t)node * DREP + tid] = ub;
    }
}

// ---------------- classifier: logit = h @ mlp_w^T + b; log_softmax; copy h ----------------
__global__ void __launch_bounds__(256) cls_kernel(
    const float* __restrict__ h, const float* __restrict__ mw,
    const float* __restrict__ mb, float* __restrict__ outLogp,
    float* __restrict__ outH, int N)
{
    __shared__ float lgs[8][17];
    const int w = threadIdx.x >> 5, lane = threadIdx.x & 31;
    const int node = blockIdx.x * 8 + w;
    if (node >= N) return;

    float hreg[8];
#pragma unroll
    for (int j = 0; j < 8; j++) hreg[j] = h[(size_t)node * DREP + j * 32 + lane];
    if (outH) {
#pragma unroll
        for (int j = 0; j < 8; j++) outH[(size_t)node * DREP + j * 32 + lane] = hreg[j];
    }

    float logit[NCLS];
#pragma unroll
    for (int c = 0; c < NCLS; c++) {
        float a = 0.f;
#pragma unroll
        for (int j = 0; j < 8; j++)
            a = fmaf(hreg[j], mw[c * DREP + j * 32 + lane], a);
        a += __shfl_xor_sync(0xffffffffu, a, 16);
        a += __shfl_xor_sync(0xffffffffu, a, 8);
        a += __shfl_xor_sync(0xffffffffu, a, 4);
        a += __shfl_xor_sync(0xffffffffu, a, 2);
        a += __shfl_xor_sync(0xffffffffu, a, 1);
        logit[c] = a + mb[c];
    }
    float mx = logit[0];
#pragma unroll
    for (int c = 1; c < NCLS; c++) mx = fmaxf(mx, logit[c]);
    float ssum = 0.f;
#pragma unroll
    for (int c = 0; c < NCLS; c++) ssum += expf(logit[c] - mx);
    float L = mx + logf(ssum);
    if (lane == 0) {
#pragma unroll
        for (int c = 0; c < NCLS; c++) lgs[w][c] = logit[c];
    }
    __syncwarp();
    if (lane < NCLS)
        outLogp[(size_t)node * NCLS + lane] = lgs[w][lane] - L;
}

__global__ void copy_kernel(const float* __restrict__ src, float* __restrict__ dst, int n)
{
    int i = blockIdx.x * blockDim.x + threadIdx.x;
    if (i < n) dst[i] = src[i];
}

// ---------------- launch ----------------
extern "C" void kernel_launch(void* const* d_in, const int* in_sizes, int n_in,
                              void* d_out, int out_size)
{
    const float* x         = (const float*)d_in[0];
    const int*   nbrs      = (const int*)  d_in[1];
    const float* pca_w     = (const float*)d_in[2];
    const float* pca_b     = (const float*)d_in[3];
    const float* raw_param = (const float*)d_in[4];
    const float* fc_w      = (const float*)d_in[5];
    const float* fc_b      = (const float*)d_in[6];
    const float* mlp_w     = (const float*)d_in[7];
    const float* mlp_b     = (const float*)d_in[8];
    const int*   routit    = (n_in > 9) ? (const int*)d_in[9] : nullptr;

    const int N = in_sizes[0] / NFEAT;

    float *bufA, *bufB, *bufC;
    cudaGetSymbolAddress((void**)&bufA, g_bufA);
    cudaGetSymbolAddress((void**)&bufB, g_bufB);
    cudaGetSymbolAddress((void**)&bufC, g_bufC);

    // 1) h0 = relu(x @ pca_w + pca_b)
    dim3 pgrid((N + 127) / 128, DREP / 128);
    pca_kernel<<<pgrid, 256>>>(x, pca_w, pca_b, bufA, N);

    // 2) layer-0 front end: l2norm -> per-capsule fc -> relu -> l2norm
    fcnorm_kernel<<<(N + 7) / 8, 256>>>(bufA, fc_w, fc_b, bufB, N);

    // 3) three routing layers (intermediate relu+l2norm fused in epilogue)
    route_kernel<<<N, 256>>>(bufB, nbrs, raw_param, routit, bufA, 0, N);
    route_kernel<<<N, 256>>>(bufA, nbrs, raw_param, routit, bufB, 0, N);
    route_kernel<<<N, 256>>>(bufB, nbrs, raw_param, routit, bufC, 1, N);

    // 4) classifier + output assembly (adaptive to harness output layout)
    float* out = (float*)d_out;
    if (out_size == N * (NCLS + DREP)) {
        cls_kernel<<<(N + 7) / 8, 256>>>(bufC, mlp_w, mlp_b, out, out + (size_t)N * NCLS, N);
    } else if (out_size == N * NCLS) {
        cls_kernel<<<(N + 7) / 8, 256>>>(bufC, mlp_w, mlp_b, out, nullptr, N);
    } else {
        int n = N * DREP;
        copy_kernel<<<(n + 255) / 256, 256>>>(bufC, out, n);
    }
}